// round 1
// baseline (speedup 1.0000x reference)
#include <cuda_runtime.h>
#include <math.h>

#define BATCH 64
#define EDIM 1024
#define HDIM 1024
#define FDIM 2048
#define VDIM 32000
#define NLAYER 8

// ---------------- scratch (no allocation allowed) ----------------
__device__ __align__(16) float g_xe[BATCH * EDIM];
__device__ __align__(16) float g_feat[BATCH * HDIM];
__device__ __align__(16) float g_attn[BATCH * HDIM];
__device__ __align__(16) float g_tmp[BATCH * HDIM];
__device__ __align__(16) float g_gi[BATCH * 3 * HDIM];
__device__ __align__(16) float g_gh[BATCH * 3 * HDIM];

// ---------------- embedding gather + relu ----------------
__global__ void embed_relu_kernel(const float* __restrict__ emb,
                                  const int* __restrict__ x,
                                  float* __restrict__ xe) {
    const int b = blockIdx.x;
    const int row = x[b];
    const float* src = emb + (size_t)row * EDIM;
    float* dst = xe + (size_t)b * EDIM;
    for (int e = threadIdx.x; e < EDIM; e += blockDim.x) {
        float v = src[e];
        dst[e] = v > 0.f ? v : 0.f;
    }
}

// ---------------- skinny SGEMM: C[64,N] = act((A(+A2)) @ W^T + bias) ----------------
// A: [64,K] row-major, W: [N,K] row-major, C: [64,N] row-major.
// BM=64 (all batches in one block row), BN columns per block, BK=32.
// 256 threads, TN=4, TM = 64*BN/(256*4).
template <int BN, int EPI>  // EPI: 0 = none, 1 = relu
__global__ __launch_bounds__(256) void sgemm64_kernel(
    const float* __restrict__ A, const float* __restrict__ A2,
    const float* __restrict__ W, const float* __restrict__ bias,
    float* __restrict__ C, int K, int N) {
    constexpr int BM = 64;
    constexpr int BK = 32;
    constexpr int TN = 4;
    constexpr int TM = (BM * BN) / (256 * TN);

    __shared__ float As[BK][BM + 1];
    __shared__ float Ws[BK][BN + 1];

    const int tid = threadIdx.x;
    const int nBlock = blockIdx.x * BN;

    const int threadCol = tid % (BN / TN);
    const int threadRow = tid / (BN / TN);

    // load indexing: tiles are (rows x BK) with float4 along K
    const int ldK4 = tid % (BK / 4);   // 0..7
    const int ldRow = tid / (BK / 4);  // 0..31

    float acc[TM][TN] = {};

    for (int k0 = 0; k0 < K; k0 += BK) {
        // ---- load A tile (64 x 32), optionally fused A+A2 ----
#pragma unroll
        for (int mm = 0; mm < BM; mm += 32) {
            const int m = ldRow + mm;
            float4 v = *reinterpret_cast<const float4*>(
                &A[(size_t)m * K + k0 + ldK4 * 4]);
            if (A2) {
                float4 v2 = *reinterpret_cast<const float4*>(
                    &A2[(size_t)m * K + k0 + ldK4 * 4]);
                v.x += v2.x; v.y += v2.y; v.z += v2.z; v.w += v2.w;
            }
            As[ldK4 * 4 + 0][m] = v.x;
            As[ldK4 * 4 + 1][m] = v.y;
            As[ldK4 * 4 + 2][m] = v.z;
            As[ldK4 * 4 + 3][m] = v.w;
        }
        // ---- load W tile (BN x 32) ----
#pragma unroll
        for (int nn = 0; nn < BN; nn += 32) {
            const int n = ldRow + nn;
            float4 v = *reinterpret_cast<const float4*>(
                &W[(size_t)(nBlock + n) * K + k0 + ldK4 * 4]);
            Ws[ldK4 * 4 + 0][n] = v.x;
            Ws[ldK4 * 4 + 1][n] = v.y;
            Ws[ldK4 * 4 + 2][n] = v.z;
            Ws[ldK4 * 4 + 3][n] = v.w;
        }
        __syncthreads();

#pragma unroll
        for (int k = 0; k < BK; k++) {
            float rm[TM], rn[TN];
#pragma unroll
            for (int i = 0; i < TM; i++) rm[i] = As[k][threadRow * TM + i];
#pragma unroll
            for (int j = 0; j < TN; j++) rn[j] = Ws[k][threadCol * TN + j];
#pragma unroll
            for (int i = 0; i < TM; i++)
#pragma unroll
                for (int j = 0; j < TN; j++) acc[i][j] = fmaf(rm[i], rn[j], acc[i][j]);
        }
        __syncthreads();
    }

#pragma unroll
    for (int i = 0; i < TM; i++) {
        const int b = threadRow * TM + i;
#pragma unroll
        for (int j = 0; j < TN; j++) {
            const int n = nBlock + threadCol * TN + j;
            float v = acc[i][j] + bias[n];
            if (EPI == 1) v = fmaxf(v, 0.f);
            C[(size_t)b * N + n] = v;
        }
    }
}

// ---------------- GRU gate fusion ----------------
// out = (1-z)*n + z*(hid+attn), gates from gi/gh [64, 3H]
__global__ void gru_gate_kernel(const float* __restrict__ gi,
                                const float* __restrict__ gh,
                                const float* __restrict__ hid,
                                const float* __restrict__ attn,
                                float* __restrict__ out,
                                float* __restrict__ out2) {
    const int idx = blockIdx.x * blockDim.x + threadIdx.x;  // b*H + h
    if (idx >= BATCH * HDIM) return;
    const int b = idx / HDIM;
    const int h = idx - b * HDIM;
    const size_t base = (size_t)b * 3 * HDIM + h;
    const float ir = gi[base];
    const float iz = gi[base + HDIM];
    const float in_ = gi[base + 2 * HDIM];
    const float hr = gh[base];
    const float hz = gh[base + HDIM];
    const float hn = gh[base + 2 * HDIM];

    const float r = 1.f / (1.f + expf(-(ir + hr)));
    const float z = 1.f / (1.f + expf(-(iz + hz)));
    const float n = tanhf(in_ + r * hn);
    const float hp = hid[idx] + attn[idx];
    const float o = (1.f - z) * n + z * hp;
    out[idx] = o;
    if (out2) out2[idx] = o;
}

// ---------------- in-place log_softmax over rows of [64, V] ----------------
__global__ __launch_bounds__(1024) void log_softmax_kernel(float* __restrict__ logits) {
    const int b = blockIdx.x;
    float* row = logits + (size_t)b * VDIM;
    __shared__ float sred[32];
    __shared__ float s_val;
    const int lane = threadIdx.x & 31;
    const int wid = threadIdx.x >> 5;

    // pass 1: max
    float m = -1e30f;
    for (int v = threadIdx.x; v < VDIM; v += blockDim.x) m = fmaxf(m, row[v]);
#pragma unroll
    for (int o = 16; o; o >>= 1) m = fmaxf(m, __shfl_xor_sync(0xffffffffu, m, o));
    if (lane == 0) sred[wid] = m;
    __syncthreads();
    if (wid == 0) {
        float t = (lane < (blockDim.x >> 5)) ? sred[lane] : -1e30f;
#pragma unroll
        for (int o = 16; o; o >>= 1) t = fmaxf(t, __shfl_xor_sync(0xffffffffu, t, o));
        if (lane == 0) s_val = t;
    }
    __syncthreads();
    const float mx = s_val;

    // pass 2: sum(exp)
    float sum = 0.f;
    for (int v = threadIdx.x; v < VDIM; v += blockDim.x) sum += expf(row[v] - mx);
#pragma unroll
    for (int o = 16; o; o >>= 1) sum += __shfl_xor_sync(0xffffffffu, sum, o);
    if (lane == 0) sred[wid] = sum;
    __syncthreads();
    if (wid == 0) {
        float t = (lane < (blockDim.x >> 5)) ? sred[lane] : 0.f;
#pragma unroll
        for (int o = 16; o; o >>= 1) t += __shfl_xor_sync(0xffffffffu, t, o);
        if (lane == 0) s_val = mx + logf(t);
    }
    __syncthreads();
    const float lse = s_val;

    // pass 3: write
    for (int v = threadIdx.x; v < VDIM; v += blockDim.x) row[v] -= lse;
}

// ---------------- launch ----------------
extern "C" void kernel_launch(void* const* d_in, const int* in_sizes, int n_in,
                              void* d_out, int out_size) {
    const float* feature   = (const float*)d_in[0];   // [B,F]
    const int*   x         = (const int*)d_in[1];     // [B]
    const float* attention = (const float*)d_in[2];   // [B,H]
    const float* hiddens   = (const float*)d_in[3];   // [NL,B,H]
    const float* emb       = (const float*)d_in[4];   // [V,E]
    const float* map_W     = (const float*)d_in[5];   // [H,F]
    const float* map_b     = (const float*)d_in[6];
    const float* ai_W      = (const float*)d_in[7];
    const float* ai_b      = (const float*)d_in[8];
    const float* ah_W      = (const float*)d_in[9];
    const float* ah_b      = (const float*)d_in[10];
    const float* ao_W      = (const float*)d_in[11];
    const float* ao_b      = (const float*)d_in[12];
    const float* gru_Wih   = (const float*)d_in[13];  // [NL,3H,E]
    const float* gru_Whh   = (const float*)d_in[14];  // [NL,3H,H]
    const float* gru_bih   = (const float*)d_in[15];  // [NL,3H]
    const float* gru_bhh   = (const float*)d_in[16];  // [NL,3H]
    const float* out_W     = (const float*)d_in[17];  // [V,H]
    const float* out_b     = (const float*)d_in[18];  // [V]

    float* out = (float*)d_out;
    float* logp = out;                      // [B,V]
    float* h1   = out + (size_t)BATCH * VDIM;       // [B,H]
    float* nh   = h1 + (size_t)BATCH * HDIM;        // [NL,B,H]

    float *xe, *feat, *attn, *tmp, *gi, *gh;
    cudaGetSymbolAddress((void**)&xe, g_xe);
    cudaGetSymbolAddress((void**)&feat, g_feat);
    cudaGetSymbolAddress((void**)&attn, g_attn);
    cudaGetSymbolAddress((void**)&tmp, g_tmp);
    cudaGetSymbolAddress((void**)&gi, g_gi);
    cudaGetSymbolAddress((void**)&gh, g_gh);

    // 1) embedding gather + relu
    embed_relu_kernel<<<BATCH, 256>>>(emb, x, xe);

    // 2) feat = relu(feature @ map_W^T + map_b)     K=2048, N=1024
    sgemm64_kernel<32, 1><<<HDIM / 32, 256>>>(feature, nullptr, map_W, map_b,
                                              feat, FDIM, HDIM);
    // 3) attn mlp chain (all K=1024, N=1024)
    sgemm64_kernel<32, 1><<<HDIM / 32, 256>>>(feat, attention, ai_W, ai_b,
                                              attn, HDIM, HDIM);
    sgemm64_kernel<32, 1><<<HDIM / 32, 256>>>(attn, nullptr, ah_W, ah_b,
                                              tmp, HDIM, HDIM);
    sgemm64_kernel<32, 1><<<HDIM / 32, 256>>>(tmp, nullptr, ao_W, ao_b,
                                              attn, HDIM, HDIM);

    // 4) 8 GRU cells. Cell inputs:
    //    L0: xe | L1: out0 | L2: out1 | L3: out1+out2 | L4: out2+out3
    //    L5: out3+out4 | L6: out4+out5 | L7: out5+out6
    const float* inA[NLAYER];
    const float* inA2[NLAYER];
    inA[0] = xe;                      inA2[0] = nullptr;
    inA[1] = nh + 0 * BATCH * HDIM;   inA2[1] = nullptr;
    inA[2] = nh + 1 * BATCH * HDIM;   inA2[2] = nullptr;
    inA[3] = nh + 1 * BATCH * HDIM;   inA2[3] = nh + 2 * BATCH * HDIM;
    inA[4] = nh + 2 * BATCH * HDIM;   inA2[4] = nh + 3 * BATCH * HDIM;
    inA[5] = nh + 3 * BATCH * HDIM;   inA2[5] = nh + 4 * BATCH * HDIM;
    inA[6] = nh + 4 * BATCH * HDIM;   inA2[6] = nh + 5 * BATCH * HDIM;
    inA[7] = nh + 5 * BATCH * HDIM;   inA2[7] = nh + 6 * BATCH * HDIM;

    for (int i = 0; i < NLAYER; i++) {
        const float* Wih = gru_Wih + (size_t)i * 3 * HDIM * EDIM;
        const float* Whh = gru_Whh + (size_t)i * 3 * HDIM * HDIM;
        const float* bih = gru_bih + (size_t)i * 3 * HDIM;
        const float* bhh = gru_bhh + (size_t)i * 3 * HDIM;
        const float* hid = hiddens + (size_t)i * BATCH * HDIM;

        // gi = xin @ Wih^T + bih   (K=1024, N=3072)
        sgemm64_kernel<32, 0><<<3 * HDIM / 32, 256>>>(inA[i], inA2[i], Wih, bih,
                                                      gi, EDIM, 3 * HDIM);
        // gh = (hid + attn) @ Whh^T + bhh
        sgemm64_kernel<32, 0><<<3 * HDIM / 32, 256>>>(hid, attn, Whh, bhh,
                                                      gh, HDIM, 3 * HDIM);
        // gates -> nh[i] (layer 0 also copies to h1 slot)
        gru_gate_kernel<<<(BATCH * HDIM) / 256, 256>>>(
            gi, gh, hid, attn, nh + (size_t)i * BATCH * HDIM,
            (i == 0) ? h1 : nullptr);
    }

    // 5) logits = x8 @ out_W^T + out_b  (K=1024, N=32000), then log-softmax
    sgemm64_kernel<64, 0><<<VDIM / 64, 256>>>(nh + 7 * (size_t)BATCH * HDIM,
                                              nullptr, out_W, out_b, logp,
                                              HDIM, VDIM);
    log_softmax_kernel<<<BATCH, 1024>>>(logp);
}

// round 2
// speedup vs baseline: 2.9715x; 2.9715x over previous
#include <cuda_runtime.h>
#include <math.h>
#include <stdint.h>

#define BATCH 64
#define EDIM 1024
#define HDIM 1024
#define FDIM 2048
#define VDIM 32000
#define NLAYER 8
#define BK 32

// ---------------- scratch (no allocation allowed) ----------------
__device__ __align__(16) float g_xe[BATCH * EDIM];
__device__ __align__(16) float g_feat[BATCH * HDIM];
__device__ __align__(16) float g_attn[BATCH * HDIM];
__device__ __align__(16) float g_tmp[BATCH * HDIM];
__device__ __align__(16) float g_gi[BATCH * 3 * HDIM];
__device__ __align__(16) float g_gh[NLAYER * BATCH * 3 * HDIM];   // all 8 layers precomputed
__device__ __align__(16) float g_part[8 * BATCH * HDIM];          // split-K partials

__device__ __forceinline__ float to_tf32(float x) {
    uint32_t u;
    asm("cvt.rna.tf32.f32 %0, %1;" : "=r"(u) : "f"(x));
    return __uint_as_float(u);
}

// ---------------- embedding gather + relu ----------------
__global__ void embed_relu_kernel(const float* __restrict__ emb,
                                  const int* __restrict__ x,
                                  float* __restrict__ xe) {
    const int b = blockIdx.x;
    const int row = x[b];
    const float* src = emb + (size_t)row * EDIM;
    float* dst = xe + (size_t)b * EDIM;
    for (int e = threadIdx.x; e < EDIM; e += blockDim.x) {
        float v = src[e];
        dst[e] = v > 0.f ? v : 0.f;
    }
}

// ---------------- tf32 tensor-core GEMM ----------------
// C[64, N] = (A (+A2)) @ W^T (+ bias when not split-K)
// A: [64,K] row-major, W: [N,K] row-major.
// blockIdx.y = batched-op index (A += y*strideA, W += y*N*K, bias += y*N, out += y*64*N)
// blockIdx.z = split-K chunk (writes raw partials to out + z*64*N, no bias)
// 256 threads = 8 warps: wm = warp&3 over M (4x16=64), wn = warp>>2 over N (2 x BN/2).
template <int BN>
__global__ __launch_bounds__(256) void gemm_tf32(
    const float* __restrict__ A, const float* __restrict__ A2,
    const float* __restrict__ W, const float* __restrict__ bias,
    float* __restrict__ out, int K, int N, int kLen, int strideA) {
    constexpr int NT = BN / 16;          // n-subtiles (8 wide) per warp
    constexpr int AS_S = 64 * 8 + 2;     // per-kstep slab stride (pad 2 -> conflict free)
    constexpr int WS_S = BN * 8 + 2;

    __shared__ float As[4 * AS_S];
    __shared__ float Ws[4 * WS_S];

    const int y = blockIdx.y;
    A += (size_t)y * strideA;
    W += (size_t)y * N * K;
    bias += (size_t)y * N;
    out += (size_t)y * BATCH * N;

    const int z = blockIdx.z;
    const bool split = (gridDim.z > 1);
    const int kBase = z * kLen;
    if (split) out += (size_t)z * BATCH * N;

    const int tid = threadIdx.x;
    const int lane = tid & 31;
    const int warp = tid >> 5;
    const int wm = warp & 3;
    const int wn = warp >> 2;
    const int nBlock = blockIdx.x * BN;

    // gmem->smem producer indexing (float4 along K)
    const int ldK4 = tid & 7;    // which group of 4 k's
    const int ldRow = tid >> 3;  // 0..31
    const int s_w = ldK4 >> 1;   // k-step slab
    const int h_w = ldK4 & 1;    // k half (0: k<4, 1: k>=4 within step)

    // mma fragment indexing
    const int r = lane >> 2;   // 0..7
    const int kk = lane & 3;   // 0..3

    float acc[NT][4];
#pragma unroll
    for (int i = 0; i < NT; i++)
#pragma unroll
        for (int j = 0; j < 4; j++) acc[i][j] = 0.f;

    for (int k0 = kBase; k0 < kBase + kLen; k0 += BK) {
        // ---- A tile (64 x 32), fragment-packed, optional fused add ----
#pragma unroll
        for (int mm = 0; mm < 64; mm += 32) {
            const int m = ldRow + mm;
            float4 v = *reinterpret_cast<const float4*>(A + (size_t)m * K + k0 + ldK4 * 4);
            if (A2) {
                float4 w = *reinterpret_cast<const float4*>(A2 + (size_t)m * K + k0 + ldK4 * 4);
                v.x += w.x; v.y += w.y; v.z += w.z; v.w += w.w;
            }
            float* d = &As[s_w * AS_S + m * 8 + h_w];
            d[0] = to_tf32(v.x); d[2] = to_tf32(v.y);
            d[4] = to_tf32(v.z); d[6] = to_tf32(v.w);
        }
        // ---- W tile (BN x 32), fragment-packed ----
#pragma unroll
        for (int nn = 0; nn < BN; nn += 32) {
            const int n = ldRow + nn;
            float4 v = *reinterpret_cast<const float4*>(W + (size_t)(nBlock + n) * K + k0 + ldK4 * 4);
            float* d = &Ws[s_w * WS_S + n * 8 + h_w];
            d[0] = to_tf32(v.x); d[2] = to_tf32(v.y);
            d[4] = to_tf32(v.z); d[6] = to_tf32(v.w);
        }
        __syncthreads();

#pragma unroll
        for (int s = 0; s < 4; s++) {
            const float* pa = &As[s * AS_S + (wm * 16 + r) * 8 + kk * 2];
            const float a0 = pa[0], a2 = pa[1];     // row r,  k / k+4
            const float a1 = pa[64], a3 = pa[65];   // row r+8
#pragma unroll
            for (int nt = 0; nt < NT; nt++) {
                const float* pb = &Ws[s * WS_S + (wn * (BN / 2) + nt * 8 + r) * 8 + kk * 2];
                const float b0 = pb[0], b1 = pb[1];
                asm volatile(
                    "mma.sync.aligned.m16n8k8.row.col.f32.tf32.tf32.f32 "
                    "{%0,%1,%2,%3}, {%4,%5,%6,%7}, {%8,%9}, {%0,%1,%2,%3};\n"
                    : "+f"(acc[nt][0]), "+f"(acc[nt][1]),
                      "+f"(acc[nt][2]), "+f"(acc[nt][3])
                    : "r"(__float_as_uint(a0)), "r"(__float_as_uint(a1)),
                      "r"(__float_as_uint(a2)), "r"(__float_as_uint(a3)),
                      "r"(__float_as_uint(b0)), "r"(__float_as_uint(b1)));
            }
        }
        __syncthreads();
    }

    // ---- epilogue ----
    const int row0 = wm * 16 + r;
#pragma unroll
    for (int nt = 0; nt < NT; nt++) {
        const int col = nBlock + wn * (BN / 2) + nt * 8 + 2 * kk;
        float v0 = acc[nt][0], v1 = acc[nt][1], v2 = acc[nt][2], v3 = acc[nt][3];
        if (!split) {
            const float b0v = bias[col], b1v = bias[col + 1];
            v0 += b0v; v1 += b1v; v2 += b0v; v3 += b1v;
        }
        *reinterpret_cast<float2*>(out + (size_t)row0 * N + col) = make_float2(v0, v1);
        *reinterpret_cast<float2*>(out + (size_t)(row0 + 8) * N + col) = make_float2(v2, v3);
    }
}

// ---------------- split-K reduction + bias + optional relu ----------------
__global__ void reduce_kernel(const float* __restrict__ part,
                              const float* __restrict__ bias,
                              float* __restrict__ out, int N, int KS, int relu) {
    const int idx = blockIdx.x * blockDim.x + threadIdx.x;  // < 64*N
    float s = 0.f;
    for (int z = 0; z < KS; z++) s += part[(size_t)z * BATCH * N + idx];
    s += bias[idx & (N - 1)];  // N power of 2 (1024)
    if (relu) s = fmaxf(s, 0.f);
    out[idx] = s;
}

// ---------------- GRU gate fusion ----------------
__global__ void gru_gate_kernel(const float* __restrict__ gi,
                                const float* __restrict__ gh,
                                const float* __restrict__ hid,
                                const float* __restrict__ attn,
                                float* __restrict__ out,
                                float* __restrict__ out2) {
    const int idx = blockIdx.x * blockDim.x + threadIdx.x;  // b*H + h
    if (idx >= BATCH * HDIM) return;
    const int b = idx >> 10;
    const int h = idx & (HDIM - 1);
    const size_t base = (size_t)b * 3 * HDIM + h;
    const float ir = gi[base];
    const float iz = gi[base + HDIM];
    const float in_ = gi[base + 2 * HDIM];
    const float hr = gh[base];
    const float hz = gh[base + HDIM];
    const float hn = gh[base + 2 * HDIM];

    const float rr = 1.f / (1.f + expf(-(ir + hr)));
    const float zz = 1.f / (1.f + expf(-(iz + hz)));
    const float nn = tanhf(in_ + rr * hn);
    const float hp = hid[idx] + attn[idx];
    const float o = (1.f - zz) * nn + zz * hp;
    out[idx] = o;
    if (out2) out2[idx] = o;
}

// ---------------- in-place log_softmax over rows of [64, V] ----------------
__global__ __launch_bounds__(1024) void log_softmax_kernel(float* __restrict__ logits) {
    const int b = blockIdx.x;
    float* row = logits + (size_t)b * VDIM;
    __shared__ float sred[32];
    __shared__ float s_val;
    const int lane = threadIdx.x & 31;
    const int wid = threadIdx.x >> 5;

    float m = -1e30f;
    for (int v = threadIdx.x; v < VDIM; v += blockDim.x) m = fmaxf(m, row[v]);
#pragma unroll
    for (int o = 16; o; o >>= 1) m = fmaxf(m, __shfl_xor_sync(0xffffffffu, m, o));
    if (lane == 0) sred[wid] = m;
    __syncthreads();
    if (wid == 0) {
        float t = (lane < (blockDim.x >> 5)) ? sred[lane] : -1e30f;
#pragma unroll
        for (int o = 16; o; o >>= 1) t = fmaxf(t, __shfl_xor_sync(0xffffffffu, t, o));
        if (lane == 0) s_val = t;
    }
    __syncthreads();
    const float mx = s_val;

    float sum = 0.f;
    for (int v = threadIdx.x; v < VDIM; v += blockDim.x) sum += expf(row[v] - mx);
#pragma unroll
    for (int o = 16; o; o >>= 1) sum += __shfl_xor_sync(0xffffffffu, sum, o);
    if (lane == 0) sred[wid] = sum;
    __syncthreads();
    if (wid == 0) {
        float t = (lane < (blockDim.x >> 5)) ? sred[lane] : 0.f;
#pragma unroll
        for (int o = 16; o; o >>= 1) t += __shfl_xor_sync(0xffffffffu, t, o);
        if (lane == 0) s_val = mx + logf(t);
    }
    __syncthreads();
    const float lse = s_val;

    for (int v = threadIdx.x; v < VDIM; v += blockDim.x) row[v] -= lse;
}

// ---------------- launch ----------------
extern "C" void kernel_launch(void* const* d_in, const int* in_sizes, int n_in,
                              void* d_out, int out_size) {
    const float* feature   = (const float*)d_in[0];
    const int*   x         = (const int*)d_in[1];
    const float* attention = (const float*)d_in[2];
    const float* hiddens   = (const float*)d_in[3];
    const float* emb       = (const float*)d_in[4];
    const float* map_W     = (const float*)d_in[5];
    const float* map_b     = (const float*)d_in[6];
    const float* ai_W      = (const float*)d_in[7];
    const float* ai_b      = (const float*)d_in[8];
    const float* ah_W      = (const float*)d_in[9];
    const float* ah_b      = (const float*)d_in[10];
    const float* ao_W      = (const float*)d_in[11];
    const float* ao_b      = (const float*)d_in[12];
    const float* gru_Wih   = (const float*)d_in[13];
    const float* gru_Whh   = (const float*)d_in[14];
    const float* gru_bih   = (const float*)d_in[15];
    const float* gru_bhh   = (const float*)d_in[16];
    const float* out_W     = (const float*)d_in[17];
    const float* out_b     = (const float*)d_in[18];

    float* out = (float*)d_out;
    float* logp = out;                                 // [B,V]
    float* h1   = out + (size_t)BATCH * VDIM;          // [B,H]
    float* nh   = h1 + (size_t)BATCH * HDIM;           // [NL,B,H]

    float *xe, *feat, *attn, *tmp, *gi, *gh, *part;
    cudaGetSymbolAddress((void**)&xe, g_xe);
    cudaGetSymbolAddress((void**)&feat, g_feat);
    cudaGetSymbolAddress((void**)&attn, g_attn);
    cudaGetSymbolAddress((void**)&tmp, g_tmp);
    cudaGetSymbolAddress((void**)&gi, g_gi);
    cudaGetSymbolAddress((void**)&gh, g_gh);
    cudaGetSymbolAddress((void**)&part, g_part);

    // 1) embedding gather + relu
    embed_relu_kernel<<<BATCH, 256>>>(emb, x, xe);

    // 2) attention MLP chain (split-K 8 to fill the chip, reduce applies bias+relu)
    // feat = relu(feature @ map_W^T + map_b)   K=2048
    gemm_tf32<32><<<dim3(HDIM / 32, 1, 8), 256>>>(feature, nullptr, map_W, map_b,
                                                  part, FDIM, HDIM, FDIM / 8, 0);
    reduce_kernel<<<BATCH * HDIM / 256, 256>>>(part, map_b, feat, HDIM, 8, 1);
    // attn = relu((feat+attention) @ ai_W^T + ai_b)
    gemm_tf32<32><<<dim3(HDIM / 32, 1, 8), 256>>>(feat, attention, ai_W, ai_b,
                                                  part, HDIM, HDIM, HDIM / 8, 0);
    reduce_kernel<<<BATCH * HDIM / 256, 256>>>(part, ai_b, attn, HDIM, 8, 1);
    // tmp = relu(attn @ ah_W^T + ah_b)
    gemm_tf32<32><<<dim3(HDIM / 32, 1, 8), 256>>>(attn, nullptr, ah_W, ah_b,
                                                  part, HDIM, HDIM, HDIM / 8, 0);
    reduce_kernel<<<BATCH * HDIM / 256, 256>>>(part, ah_b, tmp, HDIM, 8, 1);
    // attn = relu(tmp @ ao_W^T + ao_b)
    gemm_tf32<32><<<dim3(HDIM / 32, 1, 8), 256>>>(tmp, nullptr, ao_W, ao_b,
                                                  part, HDIM, HDIM, HDIM / 8, 0);
    reduce_kernel<<<BATCH * HDIM / 256, 256>>>(part, ao_b, attn, HDIM, 8, 1);

    // 3) ALL 8 gh GEMMs in one launch: gh[i] = (hiddens[i]+attn) @ Whh[i]^T + bhh[i]
    //    (independent of the recurrence -> full-chip 768-block launch)
    gemm_tf32<32><<<dim3(3 * HDIM / 32, NLAYER, 1), 256>>>(
        hiddens, attn, gru_Whh, gru_bhh, gh, HDIM, 3 * HDIM, HDIM, BATCH * HDIM);

    // 4) sequential GRU chain: gi GEMM + gate fusion per layer
    const float* inA[NLAYER];
    const float* inA2[NLAYER];
    inA[0] = xe;                      inA2[0] = nullptr;
    inA[1] = nh + 0 * BATCH * HDIM;   inA2[1] = nullptr;
    inA[2] = nh + 1 * BATCH * HDIM;   inA2[2] = nullptr;
    inA[3] = nh + 1 * BATCH * HDIM;   inA2[3] = nh + 2 * BATCH * HDIM;
    inA[4] = nh + 2 * BATCH * HDIM;   inA2[4] = nh + 3 * BATCH * HDIM;
    inA[5] = nh + 3 * BATCH * HDIM;   inA2[5] = nh + 4 * BATCH * HDIM;
    inA[6] = nh + 4 * BATCH * HDIM;   inA2[6] = nh + 5 * BATCH * HDIM;
    inA[7] = nh + 5 * BATCH * HDIM;   inA2[7] = nh + 6 * BATCH * HDIM;

    for (int i = 0; i < NLAYER; i++) {
        const float* Wih = gru_Wih + (size_t)i * 3 * HDIM * EDIM;
        const float* bih = gru_bih + (size_t)i * 3 * HDIM;
        const float* hid = hiddens + (size_t)i * BATCH * HDIM;

        gemm_tf32<32><<<dim3(3 * HDIM / 32, 1, 1), 256>>>(
            inA[i], inA2[i], Wih, bih, gi, EDIM, 3 * HDIM, EDIM, 0);

        gru_gate_kernel<<<(BATCH * HDIM) / 256, 256>>>(
            gi, gh + (size_t)i * BATCH * 3 * HDIM, hid, attn,
            nh + (size_t)i * BATCH * HDIM, (i == 0) ? h1 : nullptr);
    }

    // 5) logits = x8 @ out_W^T + out_b  (N=32000 -> 500 blocks), then log-softmax
    gemm_tf32<64><<<dim3(VDIM / 64, 1, 1), 256>>>(
        nh + 7 * (size_t)BATCH * HDIM, nullptr, out_W, out_b, logp,
        HDIM, VDIM, HDIM, 0);
    log_softmax_kernel<<<BATCH, 1024>>>(logp);
}

// round 3
// speedup vs baseline: 5.3510x; 1.8008x over previous
#include <cuda_runtime.h>
#include <math.h>
#include <stdint.h>

#define BATCH 64
#define EDIM 1024
#define HDIM 1024
#define FDIM 2048
#define VDIM 32000
#define NLAYER 8

// ---------------- scratch (no allocation allowed) ----------------
__device__ __align__(16) float g_xe[BATCH * EDIM];
__device__ __align__(16) float g_feat[BATCH * HDIM];
__device__ __align__(16) float g_attn[BATCH * HDIM];
__device__ __align__(16) float g_tmp[BATCH * HDIM];
__device__ __align__(16) float g_fa[BATCH * HDIM];
__device__ __align__(16) float g_gh[NLAYER * BATCH * 3 * HDIM];
__device__ __align__(16) float g_hplus[NLAYER * BATCH * HDIM];
__device__ __align__(16) float g_part[8 * BATCH * HDIM];

// ---------------- ptx helpers ----------------
__device__ __forceinline__ uint32_t cvt_tf32(float x) {
    uint32_t u;
    asm("cvt.rna.tf32.f32 %0, %1;" : "=r"(u) : "f"(x));
    return u;
}
__device__ __forceinline__ void cp16(uint32_t saddr, const void* g) {
    asm volatile("cp.async.cg.shared.global [%0], [%1], 16;\n" ::"r"(saddr), "l"(g));
}
__device__ __forceinline__ void cp_commit() { asm volatile("cp.async.commit_group;\n"); }
template <int N>
__device__ __forceinline__ void cp_wait() { asm volatile("cp.async.wait_group %0;\n" ::"n"(N)); }

__device__ __forceinline__ void mma8(float* c, uint32_t a0, uint32_t a1, uint32_t a2,
                                     uint32_t a3, uint32_t b0, uint32_t b1) {
    asm volatile(
        "mma.sync.aligned.m16n8k8.row.col.f32.tf32.tf32.f32 "
        "{%0,%1,%2,%3}, {%4,%5,%6,%7}, {%8,%9}, {%0,%1,%2,%3};\n"
        : "+f"(c[0]), "+f"(c[1]), "+f"(c[2]), "+f"(c[3])
        : "r"(a0), "r"(a1), "r"(a2), "r"(a3), "r"(b0), "r"(b1));
}

// ---------------- embedding gather + relu ----------------
__global__ void embed_relu_kernel(const float* __restrict__ emb,
                                  const int* __restrict__ x,
                                  float* __restrict__ xe) {
    const int b = blockIdx.x;
    const int row = x[b];
    const float* src = emb + (size_t)row * EDIM;
    float* dst = xe + (size_t)b * EDIM;
    for (int e = threadIdx.x; e < EDIM; e += blockDim.x) {
        float v = src[e];
        dst[e] = v > 0.f ? v : 0.f;
    }
}

// ---------------- elementwise adds ----------------
__global__ void vecadd_kernel(const float* __restrict__ a, const float* __restrict__ b,
                              float* __restrict__ o, int n) {
    int i = blockIdx.x * blockDim.x + threadIdx.x;
    if (i < n) o[i] = a[i] + b[i];
}
// hplus[l,b,h] = hiddens[l,b,h] + attn[b,h]
__global__ void hplus_kernel(const float* __restrict__ hid, const float* __restrict__ attn,
                             float* __restrict__ o) {
    int i = blockIdx.x * blockDim.x + threadIdx.x;  // < NL*B*H
    o[i] = hid[i] + attn[i & (BATCH * HDIM - 1)];
}

// ---------------- pipelined tf32 GEMM: C[64,N] = A @ W^T (+bias if !split) ----------------
// A:[64,K] rm, W:[N,K] rm. blockIdx.y batches (A+=y*strideA, W+=y*N*K, bias+=y*N, out+=y*64N)
// blockIdx.z splits K (out += z*64*N, raw partials).
template <int BN>
__global__ __launch_bounds__(256) void gemm_pipe(
    const float* __restrict__ A, const float* __restrict__ W,
    const float* __restrict__ bias, float* __restrict__ out,
    int K, int N, int kLen, int strideA) {
    constexpr int S = 3;
    constexpr int LDT = 36;  // 32 + 4 pad (floats)
    constexpr int NT = BN / 16;
    extern __shared__ float sm[];
    float* As = sm;                    // S*64*LDT
    float* Ws = sm + S * 64 * LDT;     // S*BN*LDT

    const int y = blockIdx.y;
    A += (size_t)y * strideA;
    W += (size_t)y * N * K;
    bias += (size_t)y * N;
    out += (size_t)y * BATCH * N;
    const int z = blockIdx.z;
    const bool split = (gridDim.z > 1);
    const int kBase = z * kLen;
    if (split) out += (size_t)z * BATCH * N;

    const int tid = threadIdx.x, lane = tid & 31, warp = tid >> 5;
    const int wm = warp & 3, wn = warp >> 2;
    const int nBlock = blockIdx.x * BN;
    const int ldRow = tid >> 3, ldK4 = tid & 7;
    const int r = lane >> 2, kk = lane & 3;

    const uint32_t sA = (uint32_t)__cvta_generic_to_shared(As);
    const uint32_t sW = (uint32_t)__cvta_generic_to_shared(Ws);

    auto issue = [&](int st, int k0) {
#pragma unroll
        for (int mm = 0; mm < 64; mm += 32) {
            const int m = ldRow + mm;
            cp16(sA + (uint32_t)(((st * 64 + m) * LDT + ldK4 * 4) * 4),
                 A + (size_t)m * K + k0 + ldK4 * 4);
        }
#pragma unroll
        for (int nn = 0; nn < BN; nn += 32) {
            const int n = ldRow + nn;
            cp16(sW + (uint32_t)(((st * BN + n) * LDT + ldK4 * 4) * 4),
                 W + (size_t)(nBlock + n) * K + k0 + ldK4 * 4);
        }
    };

    const int nK = kLen / 32;
#pragma unroll
    for (int p = 0; p < S - 1; p++) {
        if (p < nK) issue(p, kBase + p * 32);
        cp_commit();
    }

    float acc[NT][4];
#pragma unroll
    for (int i = 0; i < NT; i++)
#pragma unroll
        for (int j = 0; j < 4; j++) acc[i][j] = 0.f;

    for (int kt = 0; kt < nK; kt++) {
        cp_wait<S - 2>();
        __syncthreads();
        const int pf = kt + S - 1;
        if (pf < nK) issue(pf % S, kBase + pf * 32);
        cp_commit();
        const float* a_ = As + (kt % S) * 64 * LDT;
        const float* w_ = Ws + (kt % S) * BN * LDT;
#pragma unroll
        for (int s = 0; s < 4; s++) {
            const int col = s * 8 + kk;
            const uint32_t a0 = cvt_tf32(a_[(wm * 16 + r) * LDT + col]);
            const uint32_t a1 = cvt_tf32(a_[(wm * 16 + r + 8) * LDT + col]);
            const uint32_t a2 = cvt_tf32(a_[(wm * 16 + r) * LDT + col + 4]);
            const uint32_t a3 = cvt_tf32(a_[(wm * 16 + r + 8) * LDT + col + 4]);
#pragma unroll
            for (int nt = 0; nt < NT; nt++) {
                const int n = wn * (BN / 2) + nt * 8 + r;
                const uint32_t b0 = cvt_tf32(w_[n * LDT + col]);
                const uint32_t b1 = cvt_tf32(w_[n * LDT + col + 4]);
                mma8(acc[nt], a0, a1, a2, a3, b0, b1);
            }
        }
    }

    const int row0 = wm * 16 + r;
#pragma unroll
    for (int nt = 0; nt < NT; nt++) {
        const int col = nBlock + wn * (BN / 2) + nt * 8 + 2 * kk;
        float v0 = acc[nt][0], v1 = acc[nt][1], v2 = acc[nt][2], v3 = acc[nt][3];
        if (!split) {
            const float b0v = bias[col], b1v = bias[col + 1];
            v0 += b0v; v1 += b1v; v2 += b0v; v3 += b1v;
        }
        *reinterpret_cast<float2*>(out + (size_t)row0 * N + col) = make_float2(v0, v1);
        *reinterpret_cast<float2*>(out + (size_t)(row0 + 8) * N + col) = make_float2(v2, v3);
    }
}

// ---------------- split-K reduction + bias + relu ----------------
__global__ void reduce_kernel(const float* __restrict__ part,
                              const float* __restrict__ bias,
                              float* __restrict__ out, int KS) {
    const int idx = blockIdx.x * blockDim.x + threadIdx.x;  // < 64*1024
    float s = 0.f;
    for (int zz = 0; zz < KS; zz++) s += part[(size_t)zz * BATCH * HDIM + idx];
    s += bias[idx & (HDIM - 1)];
    out[idx] = fmaxf(s, 0.f);
}

// ---------------- fused GRU layer: gi GEMM (3 gates x 8 dims) + gate math ----------------
// block h0 = blockIdx.x*8 gate dims; 384 threads = 12 warps (4 M-tiles x 3 sections).
template <bool HASA2>
__global__ __launch_bounds__(384) void gru_fused(
    const float* __restrict__ A, const float* __restrict__ A2,
    const float* __restrict__ Wih, const float* __restrict__ bih,
    const float* __restrict__ gh,      // [64,3H] with bhh folded
    const float* __restrict__ hplus,   // [64,H]
    float* __restrict__ outh, float* __restrict__ outh2) {
    constexpr int S = 3;
    constexpr int LDT = 36;
    constexpr int K = EDIM;
    extern __shared__ float sm[];
    float* As = sm;                           // S*64*LDT
    float* Wsf = As + S * 64 * LDT;           // S*24*LDT
    float* As2 = Wsf + S * 24 * LDT;          // S*64*LDT (if HASA2)
    float* Cs = As2 + (HASA2 ? S * 64 * LDT : 0);  // 64*26

    const int h0 = blockIdx.x * 8;
    const int tid = threadIdx.x, lane = tid & 31, warp = tid >> 5;
    const int wm = warp & 3, sec = warp >> 2;  // 12 warps exactly
    const int r = lane >> 2, kk = lane & 3;

    const uint32_t sA = (uint32_t)__cvta_generic_to_shared(As);
    const uint32_t sW = (uint32_t)__cvta_generic_to_shared(Wsf);
    const uint32_t sA2 = (uint32_t)__cvta_generic_to_shared(As2);

    auto issue = [&](int st, int k0) {
        for (int idx = tid; idx < 512; idx += 384) {  // A: 64 rows x 8 f4
            const int m = idx >> 3, k4 = idx & 7;
            const uint32_t off = (uint32_t)(((st * 64 + m) * LDT + k4 * 4) * 4);
            cp16(sA + off, A + (size_t)m * K + k0 + k4 * 4);
            if (HASA2) cp16(sA2 + off, A2 + (size_t)m * K + k0 + k4 * 4);
        }
        if (tid < 192) {  // W: 24 rows x 8 f4
            const int wr = tid >> 3, k4 = tid & 7;
            const int grow = (wr >> 3) * HDIM + h0 + (wr & 7);
            cp16(sW + (uint32_t)(((st * 24 + wr) * LDT + k4 * 4) * 4),
                 Wih + (size_t)grow * K + k0 + k4 * 4);
        }
    };

    const int nK = K / 32;  // 32
#pragma unroll
    for (int p = 0; p < S - 1; p++) { issue(p, p * 32); cp_commit(); }

    float acc[4] = {0.f, 0.f, 0.f, 0.f};
    for (int kt = 0; kt < nK; kt++) {
        cp_wait<S - 2>();
        __syncthreads();
        const int pf = kt + S - 1;
        if (pf < nK) issue(pf % S, pf * 32);
        cp_commit();
        const float* a_ = As + (kt % S) * 64 * LDT;
        const float* a2_ = As2 + (kt % S) * 64 * LDT;
        const float* w_ = Wsf + (kt % S) * 24 * LDT;
#pragma unroll
        for (int s = 0; s < 4; s++) {
            const int col = s * 8 + kk;
            float f0 = a_[(wm * 16 + r) * LDT + col];
            float f1 = a_[(wm * 16 + r + 8) * LDT + col];
            float f2 = a_[(wm * 16 + r) * LDT + col + 4];
            float f3 = a_[(wm * 16 + r + 8) * LDT + col + 4];
            if (HASA2) {
                f0 += a2_[(wm * 16 + r) * LDT + col];
                f1 += a2_[(wm * 16 + r + 8) * LDT + col];
                f2 += a2_[(wm * 16 + r) * LDT + col + 4];
                f3 += a2_[(wm * 16 + r + 8) * LDT + col + 4];
            }
            const uint32_t b0 = cvt_tf32(w_[(sec * 8 + r) * LDT + col]);
            const uint32_t b1 = cvt_tf32(w_[(sec * 8 + r) * LDT + col + 4]);
            mma8(acc, cvt_tf32(f0), cvt_tf32(f1), cvt_tf32(f2), cvt_tf32(f3), b0, b1);
        }
    }

    // stash gi tile: Cs[64][26], cols = sec*8 + {2kk,2kk+1}
    const int row0 = wm * 16 + r;
    *reinterpret_cast<float2*>(&Cs[row0 * 26 + sec * 8 + 2 * kk]) =
        make_float2(acc[0], acc[1]);
    *reinterpret_cast<float2*>(&Cs[(row0 + 8) * 26 + sec * 8 + 2 * kk]) =
        make_float2(acc[2], acc[3]);
    __syncthreads();

    for (int idx = tid; idx < 512; idx += 384) {
        const int b = idx >> 3, hh = idx & 7;
        const int h = h0 + hh;
        const float ir = Cs[b * 26 + hh] + bih[h];
        const float iz = Cs[b * 26 + 8 + hh] + bih[HDIM + h];
        const float in_ = Cs[b * 26 + 16 + hh] + bih[2 * HDIM + h];
        const float* ghb = gh + (size_t)b * 3 * HDIM + h;
        const float rr = 1.f / (1.f + expf(-(ir + ghb[0])));
        const float zz = 1.f / (1.f + expf(-(iz + ghb[HDIM])));
        const float nn = tanhf(in_ + rr * ghb[2 * HDIM]);
        const float hp = hplus[(size_t)b * HDIM + h];
        const float o = (1.f - zz) * nn + zz * hp;
        outh[(size_t)b * HDIM + h] = o;
        if (outh2) outh2[(size_t)b * HDIM + h] = o;
    }
}

// ---------------- in-place log_softmax over rows of [64, V] ----------------
__global__ __launch_bounds__(1024) void log_softmax_kernel(float* __restrict__ logits) {
    const int b = blockIdx.x;
    float* row = logits + (size_t)b * VDIM;
    __shared__ float sred[32];
    __shared__ float s_val;
    const int lane = threadIdx.x & 31;
    const int wid = threadIdx.x >> 5;

    float m = -1e30f;
    for (int v = threadIdx.x; v < VDIM; v += blockDim.x) m = fmaxf(m, row[v]);
#pragma unroll
    for (int o = 16; o; o >>= 1) m = fmaxf(m, __shfl_xor_sync(0xffffffffu, m, o));
    if (lane == 0) sred[wid] = m;
    __syncthreads();
    if (wid == 0) {
        float t = (lane < (blockDim.x >> 5)) ? sred[lane] : -1e30f;
#pragma unroll
        for (int o = 16; o; o >>= 1) t = fmaxf(t, __shfl_xor_sync(0xffffffffu, t, o));
        if (lane == 0) s_val = t;
    }
    __syncthreads();
    const float mx = s_val;

    float sum = 0.f;
    for (int v = threadIdx.x; v < VDIM; v += blockDim.x) sum += expf(row[v] - mx);
#pragma unroll
    for (int o = 16; o; o >>= 1) sum += __shfl_xor_sync(0xffffffffu, sum, o);
    if (lane == 0) sred[wid] = sum;
    __syncthreads();
    if (wid == 0) {
        float t = (lane < (blockDim.x >> 5)) ? sred[lane] : 0.f;
#pragma unroll
        for (int o = 16; o; o >>= 1) t += __shfl_xor_sync(0xffffffffu, t, o);
        if (lane == 0) s_val = mx + logf(t);
    }
    __syncthreads();
    const float lse = s_val;
    for (int v = threadIdx.x; v < VDIM; v += blockDim.x) row[v] -= lse;
}

// ---------------- launch ----------------
extern "C" void kernel_launch(void* const* d_in, const int* in_sizes, int n_in,
                              void* d_out, int out_size) {
    const float* feature   = (const float*)d_in[0];
    const int*   x         = (const int*)d_in[1];
    const float* attention = (const float*)d_in[2];
    const float* hiddens   = (const float*)d_in[3];
    const float* emb       = (const float*)d_in[4];
    const float* map_W     = (const float*)d_in[5];
    const float* map_b     = (const float*)d_in[6];
    const float* ai_W      = (const float*)d_in[7];
    const float* ai_b      = (const float*)d_in[8];
    const float* ah_W      = (const float*)d_in[9];
    const float* ah_b      = (const float*)d_in[10];
    const float* ao_W      = (const float*)d_in[11];
    const float* ao_b      = (const float*)d_in[12];
    const float* gru_Wih   = (const float*)d_in[13];
    const float* gru_Whh   = (const float*)d_in[14];
    const float* gru_bih   = (const float*)d_in[15];
    const float* gru_bhh   = (const float*)d_in[16];
    const float* out_W     = (const float*)d_in[17];
    const float* out_b     = (const float*)d_in[18];

    float* out = (float*)d_out;
    float* logp = out;                                 // [B,V]
    float* h1   = out + (size_t)BATCH * VDIM;          // [B,H]
    float* nh   = h1 + (size_t)BATCH * HDIM;           // [NL,B,H]

    float *xe, *feat, *attn, *tmp, *fa, *gh, *hplus, *part;
    cudaGetSymbolAddress((void**)&xe, g_xe);
    cudaGetSymbolAddress((void**)&feat, g_feat);
    cudaGetSymbolAddress((void**)&attn, g_attn);
    cudaGetSymbolAddress((void**)&tmp, g_tmp);
    cudaGetSymbolAddress((void**)&fa, g_fa);
    cudaGetSymbolAddress((void**)&gh, g_gh);
    cudaGetSymbolAddress((void**)&hplus, g_hplus);
    cudaGetSymbolAddress((void**)&part, g_part);

    // dynamic smem sizes
    const int SM_G32 = (3 * 64 * 36 + 3 * 32 * 36) * 4;                 // 41472
    const int SM_G64 = (3 * 64 * 36 + 3 * 64 * 36) * 4;                 // 55296
    const int SM_F0  = (3 * 64 * 36 + 3 * 24 * 36) * 4 + 64 * 26 * 4;   // 44672
    const int SM_F1  = SM_F0 + 3 * 64 * 36 * 4;                         // 72320
    cudaFuncSetAttribute(gemm_pipe<64>, cudaFuncAttributeMaxDynamicSharedMemorySize, SM_G64);
    cudaFuncSetAttribute(gru_fused<true>, cudaFuncAttributeMaxDynamicSharedMemorySize, SM_F1);
    cudaFuncSetAttribute(gru_fused<false>, cudaFuncAttributeMaxDynamicSharedMemorySize, SM_F0);

    // 1) embedding gather + relu
    embed_relu_kernel<<<BATCH, 256>>>(emb, x, xe);

    // 2) attention MLP chain (split-K 8, reduce adds bias+relu)
    gemm_pipe<32><<<dim3(HDIM / 32, 1, 8), 256, SM_G32>>>(feature, map_W, map_b,
                                                          part, FDIM, HDIM, FDIM / 8, 0);
    reduce_kernel<<<BATCH * HDIM / 256, 256>>>(part, map_b, feat, 8);
    vecadd_kernel<<<BATCH * HDIM / 256, 256>>>(feat, attention, fa, BATCH * HDIM);
    gemm_pipe<32><<<dim3(HDIM / 32, 1, 8), 256, SM_G32>>>(fa, ai_W, ai_b,
                                                          part, HDIM, HDIM, HDIM / 8, 0);
    reduce_kernel<<<BATCH * HDIM / 256, 256>>>(part, ai_b, attn, 8);
    gemm_pipe<32><<<dim3(HDIM / 32, 1, 8), 256, SM_G32>>>(attn, ah_W, ah_b,
                                                          part, HDIM, HDIM, HDIM / 8, 0);
    reduce_kernel<<<BATCH * HDIM / 256, 256>>>(part, ah_b, tmp, 8);
    gemm_pipe<32><<<dim3(HDIM / 32, 1, 8), 256, SM_G32>>>(tmp, ao_W, ao_b,
                                                          part, HDIM, HDIM, HDIM / 8, 0);
    reduce_kernel<<<BATCH * HDIM / 256, 256>>>(part, ao_b, attn, 8);

    // 3) hplus = hiddens + attn (all layers)
    hplus_kernel<<<NLAYER * BATCH * HDIM / 256, 256>>>(hiddens, attn, hplus);

    // 4) ALL 8 gh GEMMs, one batched launch: gh[i] = hplus[i] @ Whh[i]^T + bhh[i]
    gemm_pipe<32><<<dim3(3 * HDIM / 32, NLAYER, 1), 256, SM_G32>>>(
        hplus, gru_Whh, gru_bhh, gh, HDIM, 3 * HDIM, HDIM, BATCH * HDIM);

    // 5) sequential fused GRU chain
    const float* inA[NLAYER];
    const float* inA2[NLAYER];
    inA[0] = xe;                      inA2[0] = nullptr;
    inA[1] = nh + 0 * BATCH * HDIM;   inA2[1] = nullptr;
    inA[2] = nh + 1 * BATCH * HDIM;   inA2[2] = nullptr;
    inA[3] = nh + 1 * BATCH * HDIM;   inA2[3] = nh + 2 * BATCH * HDIM;
    inA[4] = nh + 2 * BATCH * HDIM;   inA2[4] = nh + 3 * BATCH * HDIM;
    inA[5] = nh + 3 * BATCH * HDIM;   inA2[5] = nh + 4 * BATCH * HDIM;
    inA[6] = nh + 4 * BATCH * HDIM;   inA2[6] = nh + 5 * BATCH * HDIM;
    inA[7] = nh + 5 * BATCH * HDIM;   inA2[7] = nh + 6 * BATCH * HDIM;

    for (int i = 0; i < NLAYER; i++) {
        const float* Wih = gru_Wih + (size_t)i * 3 * HDIM * EDIM;
        const float* bih = gru_bih + (size_t)i * 3 * HDIM;
        const float* ghL = gh + (size_t)i * BATCH * 3 * HDIM;
        const float* hpL = hplus + (size_t)i * BATCH * HDIM;
        float* outh = nh + (size_t)i * BATCH * HDIM;
        float* outh2 = (i == 0) ? h1 : nullptr;
        if (inA2[i]) {
            gru_fused<true><<<HDIM / 8, 384, SM_F1>>>(inA[i], inA2[i], Wih, bih,
                                                      ghL, hpL, outh, outh2);
        } else {
            gru_fused<false><<<HDIM / 8, 384, SM_F0>>>(inA[i], nullptr, Wih, bih,
                                                       ghL, hpL, outh, outh2);
        }
    }

    // 6) logits = x8 @ out_W^T + out_b, then log-softmax
    gemm_pipe<64><<<dim3(VDIM / 64, 1, 1), 256, SM_G64>>>(
        nh + 7 * (size_t)BATCH * HDIM, out_W, out_b, logp, HDIM, VDIM, HDIM, 0);
    log_softmax_kernel<<<BATCH, 1024>>>(logp);
}

// round 4
// speedup vs baseline: 5.5163x; 1.0309x over previous
#include <cuda_runtime.h>
#include <math.h>
#include <stdint.h>

#define BATCH 64
#define EDIM 1024
#define HDIM 1024
#define FDIM 2048
#define VDIM 32000
#define NLAYER 8
#define BH (BATCH * HDIM)

// ---------------- scratch (no allocation allowed) ----------------
__device__ __align__(16) float g_xe[BATCH * EDIM];
__device__ __align__(16) float g_attn[BATCH * HDIM];
__device__ __align__(16) float g_tmp[BATCH * HDIM];
__device__ __align__(16) float g_fa[BATCH * HDIM];
__device__ __align__(16) float g_gh[NLAYER * BATCH * 3 * HDIM];
__device__ __align__(16) float g_hplus[NLAYER * BATCH * HDIM];
__device__ __align__(16) float g_part[8 * BATCH * HDIM];
__device__ int g_bar[NLAYER];

// ---------------- ptx helpers ----------------
// tf32 fast path: pass raw fp32 bits (hardware truncates mantissa -> rz)
__device__ __forceinline__ uint32_t tfb(float x) { return __float_as_uint(x); }

__device__ __forceinline__ void cp16(uint32_t saddr, const void* g) {
    asm volatile("cp.async.cg.shared.global [%0], [%1], 16;\n" ::"r"(saddr), "l"(g));
}
__device__ __forceinline__ void cp_commit() { asm volatile("cp.async.commit_group;\n"); }
template <int N>
__device__ __forceinline__ void cp_wait() { asm volatile("cp.async.wait_group %0;\n" ::"n"(N)); }

__device__ __forceinline__ void mma8(float* c, uint32_t a0, uint32_t a1, uint32_t a2,
                                     uint32_t a3, uint32_t b0, uint32_t b1) {
    asm volatile(
        "mma.sync.aligned.m16n8k8.row.col.f32.tf32.tf32.f32 "
        "{%0,%1,%2,%3}, {%4,%5,%6,%7}, {%8,%9}, {%0,%1,%2,%3};\n"
        : "+f"(c[0]), "+f"(c[1]), "+f"(c[2]), "+f"(c[3])
        : "r"(a0), "r"(a1), "r"(a2), "r"(a3), "r"(b0), "r"(b1));
}

// ---------------- small kernels ----------------
__global__ void embed_relu_kernel(const float* __restrict__ emb,
                                  const int* __restrict__ x,
                                  float* __restrict__ xe) {
    const int b = blockIdx.x;
    const int row = x[b];
    const float* src = emb + (size_t)row * EDIM;
    float* dst = xe + (size_t)b * EDIM;
    for (int e = threadIdx.x; e < EDIM; e += blockDim.x) {
        float v = src[e];
        dst[e] = v > 0.f ? v : 0.f;
    }
}

__global__ void init_bar_kernel() {
    if (threadIdx.x < NLAYER) g_bar[threadIdx.x] = 0;
}

// hplus[l,b,h] = hiddens[l,b,h] + attn[b,h]
__global__ void hplus_kernel(const float* __restrict__ hid, const float* __restrict__ attn,
                             float* __restrict__ o) {
    int i = blockIdx.x * blockDim.x + threadIdx.x;
    o[i] = hid[i] + attn[i & (BH - 1)];
}

// split-K reduce: out = relu(sum + bias) (+ add)
__global__ void reduce_kernel(const float* __restrict__ part,
                              const float* __restrict__ bias,
                              const float* __restrict__ add,
                              float* __restrict__ out, int KS) {
    const int idx = blockIdx.x * blockDim.x + threadIdx.x;  // < 64*1024
    float s = 0.f;
    for (int zz = 0; zz < KS; zz++) s += part[(size_t)zz * BH + idx];
    s += bias[idx & (HDIM - 1)];
    s = fmaxf(s, 0.f);
    if (add) s += add[idx];
    out[idx] = s;
}

// ---------------- pipelined tf32 GEMM: C[64,N] = A @ W^T (+bias if !split) ----------------
template <int BN>
__global__ __launch_bounds__(256) void gemm_pipe(
    const float* __restrict__ A, const float* __restrict__ W,
    const float* __restrict__ bias, float* __restrict__ out,
    int K, int N, int kLen, int strideA) {
    constexpr int S = 3;
    constexpr int LDT = 36;
    constexpr int NT = BN / 16;
    extern __shared__ float sm[];
    float* As = sm;
    float* Ws = sm + S * 64 * LDT;

    const int y = blockIdx.y;
    A += (size_t)y * strideA;
    W += (size_t)y * N * K;
    bias += (size_t)y * N;
    out += (size_t)y * BATCH * N;
    const int z = blockIdx.z;
    const bool split = (gridDim.z > 1);
    const int kBase = z * kLen;
    if (split) out += (size_t)z * BATCH * N;

    const int tid = threadIdx.x, lane = tid & 31, warp = tid >> 5;
    const int wm = warp & 3, wn = warp >> 2;
    const int nBlock = blockIdx.x * BN;
    const int ldRow = tid >> 3, ldK4 = tid & 7;
    const int r = lane >> 2, kk = lane & 3;

    const uint32_t sA = (uint32_t)__cvta_generic_to_shared(As);
    const uint32_t sW = (uint32_t)__cvta_generic_to_shared(Ws);

    auto issue = [&](int st, int k0) {
#pragma unroll
        for (int mm = 0; mm < 64; mm += 32) {
            const int m = ldRow + mm;
            cp16(sA + (uint32_t)(((st * 64 + m) * LDT + ldK4 * 4) * 4),
                 A + (size_t)m * K + k0 + ldK4 * 4);
        }
#pragma unroll
        for (int nn = 0; nn < BN; nn += 32) {
            const int n = ldRow + nn;
            cp16(sW + (uint32_t)(((st * BN + n) * LDT + ldK4 * 4) * 4),
                 W + (size_t)(nBlock + n) * K + k0 + ldK4 * 4);
        }
    };

    const int nK = kLen / 32;
#pragma unroll
    for (int p = 0; p < S - 1; p++) {
        if (p < nK) issue(p, kBase + p * 32);
        cp_commit();
    }

    float acc[NT][4];
#pragma unroll
    for (int i = 0; i < NT; i++)
#pragma unroll
        for (int j = 0; j < 4; j++) acc[i][j] = 0.f;

    for (int kt = 0; kt < nK; kt++) {
        cp_wait<S - 2>();
        __syncthreads();
        const int pf = kt + S - 1;
        if (pf < nK) issue(pf % S, kBase + pf * 32);
        cp_commit();
        const float* a_ = As + (kt % S) * 64 * LDT;
        const float* w_ = Ws + (kt % S) * BN * LDT;
#pragma unroll
        for (int s = 0; s < 4; s++) {
            const int col = s * 8 + kk;
            const uint32_t a0 = tfb(a_[(wm * 16 + r) * LDT + col]);
            const uint32_t a1 = tfb(a_[(wm * 16 + r + 8) * LDT + col]);
            const uint32_t a2 = tfb(a_[(wm * 16 + r) * LDT + col + 4]);
            const uint32_t a3 = tfb(a_[(wm * 16 + r + 8) * LDT + col + 4]);
#pragma unroll
            for (int nt = 0; nt < NT; nt++) {
                const int n = wn * (BN / 2) + nt * 8 + r;
                mma8(acc[nt], a0, a1, a2, a3, tfb(w_[n * LDT + col]),
                     tfb(w_[n * LDT + col + 4]));
            }
        }
    }

    const int row0 = wm * 16 + r;
#pragma unroll
    for (int nt = 0; nt < NT; nt++) {
        const int col = nBlock + wn * (BN / 2) + nt * 8 + 2 * kk;
        float v0 = acc[nt][0], v1 = acc[nt][1], v2 = acc[nt][2], v3 = acc[nt][3];
        if (!split) {
            const float b0v = bias[col], b1v = bias[col + 1];
            v0 += b0v; v1 += b1v; v2 += b0v; v3 += b1v;
        }
        *reinterpret_cast<float2*>(out + (size_t)row0 * N + col) = make_float2(v0, v1);
        *reinterpret_cast<float2*>(out + (size_t)(row0 + 8) * N + col) = make_float2(v2, v3);
    }
}

// ---------------- persistent fused GRU chain: all 8 layers, grid barrier between ----------------
// 128 blocks x 384 threads; block owns gate dims h0..h0+7 for every layer.
__global__ __launch_bounds__(384) void gru_chain(
    const float* __restrict__ xe, float* __restrict__ nh, float* __restrict__ h1,
    const float* __restrict__ gru_Wih, const float* __restrict__ gru_bih,
    const float* __restrict__ gh, const float* __restrict__ hplus) {
    constexpr int S = 3;
    constexpr int LDT = 36;
    constexpr int K = EDIM;
    extern __shared__ float sm[];
    float* As = sm;                     // S*64*LDT
    float* Wsf = As + S * 64 * LDT;     // S*24*LDT
    float* As2 = Wsf + S * 24 * LDT;    // S*64*LDT
    float* Cs = As2 + S * 64 * LDT;     // 64*26

    const int h0 = blockIdx.x * 8;
    const int tid = threadIdx.x, lane = tid & 31, warp = tid >> 5;
    const int wm = warp & 3, sec = warp >> 2;
    const int r = lane >> 2, kk = lane & 3;

    const uint32_t sA = (uint32_t)__cvta_generic_to_shared(As);
    const uint32_t sW = (uint32_t)__cvta_generic_to_shared(Wsf);
    const uint32_t sA2 = (uint32_t)__cvta_generic_to_shared(As2);

    for (int layer = 0; layer < NLAYER; layer++) {
        const float* A;
        const float* A2 = nullptr;
        switch (layer) {
            case 0: A = xe; break;
            case 1: A = nh; break;
            case 2: A = nh + BH; break;
            case 3: A = nh + BH;     A2 = nh + 2 * BH; break;
            case 4: A = nh + 2 * BH; A2 = nh + 3 * BH; break;
            case 5: A = nh + 3 * BH; A2 = nh + 4 * BH; break;
            case 6: A = nh + 4 * BH; A2 = nh + 5 * BH; break;
            default: A = nh + 5 * BH; A2 = nh + 6 * BH; break;
        }
        const bool has2 = (A2 != nullptr);
        const float* Wih = gru_Wih + (size_t)layer * 3 * HDIM * K;
        const float* bih = gru_bih + (size_t)layer * 3 * HDIM;
        const float* ghL = gh + (size_t)layer * BATCH * 3 * HDIM;
        const float* hpL = hplus + (size_t)layer * BH;
        float* outh = nh + (size_t)layer * BH;

        auto issue = [&](int st, int k0) {
            for (int idx = tid; idx < 512; idx += 384) {
                const int m = idx >> 3, k4 = idx & 7;
                const uint32_t off = (uint32_t)(((st * 64 + m) * LDT + k4 * 4) * 4);
                cp16(sA + off, A + (size_t)m * K + k0 + k4 * 4);
                if (has2) cp16(sA2 + off, A2 + (size_t)m * K + k0 + k4 * 4);
            }
            if (tid < 192) {
                const int wr = tid >> 3, k4 = tid & 7;
                const int grow = (wr >> 3) * HDIM + h0 + (wr & 7);
                cp16(sW + (uint32_t)(((st * 24 + wr) * LDT + k4 * 4) * 4),
                     Wih + (size_t)grow * K + k0 + k4 * 4);
            }
        };

        const int nK = K / 32;
#pragma unroll
        for (int p = 0; p < S - 1; p++) { issue(p, p * 32); cp_commit(); }

        float acc[4] = {0.f, 0.f, 0.f, 0.f};
        for (int kt = 0; kt < nK; kt++) {
            cp_wait<S - 2>();
            __syncthreads();
            const int pf = kt + S - 1;
            if (pf < nK) issue(pf % S, pf * 32);
            cp_commit();
            const float* a_ = As + (kt % S) * 64 * LDT;
            const float* a2_ = As2 + (kt % S) * 64 * LDT;
            const float* w_ = Wsf + (kt % S) * 24 * LDT;
#pragma unroll
            for (int s = 0; s < 4; s++) {
                const int col = s * 8 + kk;
                float f0 = a_[(wm * 16 + r) * LDT + col];
                float f1 = a_[(wm * 16 + r + 8) * LDT + col];
                float f2 = a_[(wm * 16 + r) * LDT + col + 4];
                float f3 = a_[(wm * 16 + r + 8) * LDT + col + 4];
                if (has2) {
                    f0 += a2_[(wm * 16 + r) * LDT + col];
                    f1 += a2_[(wm * 16 + r + 8) * LDT + col];
                    f2 += a2_[(wm * 16 + r) * LDT + col + 4];
                    f3 += a2_[(wm * 16 + r + 8) * LDT + col + 4];
                }
                mma8(acc, tfb(f0), tfb(f1), tfb(f2), tfb(f3),
                     tfb(w_[(sec * 8 + r) * LDT + col]),
                     tfb(w_[(sec * 8 + r) * LDT + col + 4]));
            }
        }
        cp_wait<0>();

        const int row0 = wm * 16 + r;
        *reinterpret_cast<float2*>(&Cs[row0 * 26 + sec * 8 + 2 * kk]) =
            make_float2(acc[0], acc[1]);
        *reinterpret_cast<float2*>(&Cs[(row0 + 8) * 26 + sec * 8 + 2 * kk]) =
            make_float2(acc[2], acc[3]);
        __syncthreads();

        for (int idx = tid; idx < 512; idx += 384) {
            const int b = idx >> 3, hh = idx & 7;
            const int h = h0 + hh;
            const float ir = Cs[b * 26 + hh] + bih[h];
            const float iz = Cs[b * 26 + 8 + hh] + bih[HDIM + h];
            const float in_ = Cs[b * 26 + 16 + hh] + bih[2 * HDIM + h];
            const float* ghb = ghL + (size_t)b * 3 * HDIM + h;
            const float rr = 1.f / (1.f + expf(-(ir + ghb[0])));
            const float zz = 1.f / (1.f + expf(-(iz + ghb[HDIM])));
            const float nn = tanhf(in_ + rr * ghb[2 * HDIM]);
            const float hp = hpL[(size_t)b * HDIM + h];
            const float o = (1.f - zz) * nn + zz * hp;
            outh[(size_t)b * HDIM + h] = o;
            if (layer == 0) h1[(size_t)b * HDIM + h] = o;
        }

        // ---- grid barrier (all 128 blocks resident: 1 wave guaranteed) ----
        if (layer < NLAYER - 1) {
            __threadfence();
            __syncthreads();
            if (tid == 0) {
                atomicAdd(&g_bar[layer], 1);
                while (atomicAdd(&g_bar[layer], 0) < (int)gridDim.x) __nanosleep(32);
            }
            __syncthreads();
        }
    }
}

// ---------------- 2-pass online log_softmax over rows of [64, V] ----------------
__global__ __launch_bounds__(1024) void log_softmax_kernel(float* __restrict__ logits) {
    const int b = blockIdx.x;
    float* row = logits + (size_t)b * VDIM;
    __shared__ float smax[32], ssum[32];
    __shared__ float s_lse;
    const int lane = threadIdx.x & 31;
    const int wid = threadIdx.x >> 5;

    float m = -1e30f, s = 0.f;
    const float4* r4 = reinterpret_cast<const float4*>(row);
    for (int v = threadIdx.x; v < VDIM / 4; v += blockDim.x) {
        float4 x = r4[v];
#define ONE(val) { float d = (val) - m; \
        if (d > 0.f) { s = s * __expf(-d) + 1.f; m = (val); } else s += __expf(d); }
        ONE(x.x) ONE(x.y) ONE(x.z) ONE(x.w)
#undef ONE
    }
#pragma unroll
    for (int o = 16; o; o >>= 1) {
        float mo = __shfl_xor_sync(0xffffffffu, m, o);
        float so = __shfl_xor_sync(0xffffffffu, s, o);
        float mn = fmaxf(m, mo);
        s = s * __expf(m - mn) + so * __expf(mo - mn);
        m = mn;
    }
    if (lane == 0) { smax[wid] = m; ssum[wid] = s; }
    __syncthreads();
    if (wid == 0) {
        float mm = (lane < (blockDim.x >> 5)) ? smax[lane] : -1e30f;
        float ss = (lane < (blockDim.x >> 5)) ? ssum[lane] : 0.f;
#pragma unroll
        for (int o = 16; o; o >>= 1) {
            float mo = __shfl_xor_sync(0xffffffffu, mm, o);
            float so = __shfl_xor_sync(0xffffffffu, ss, o);
            float mn = fmaxf(mm, mo);
            ss = ss * __expf(mm - mn) + so * __expf(mo - mn);
            mm = mn;
        }
        if (lane == 0) s_lse = mm + logf(ss);
    }
    __syncthreads();
    const float lse = s_lse;
    float4* w4 = reinterpret_cast<float4*>(row);
    for (int v = threadIdx.x; v < VDIM / 4; v += blockDim.x) {
        float4 x = w4[v];
        x.x -= lse; x.y -= lse; x.z -= lse; x.w -= lse;
        w4[v] = x;
    }
}

// ---------------- launch ----------------
extern "C" void kernel_launch(void* const* d_in, const int* in_sizes, int n_in,
                              void* d_out, int out_size) {
    const float* feature   = (const float*)d_in[0];
    const int*   x         = (const int*)d_in[1];
    const float* attention = (const float*)d_in[2];
    const float* hiddens   = (const float*)d_in[3];
    const float* emb       = (const float*)d_in[4];
    const float* map_W     = (const float*)d_in[5];
    const float* map_b     = (const float*)d_in[6];
    const float* ai_W      = (const float*)d_in[7];
    const float* ai_b      = (const float*)d_in[8];
    const float* ah_W      = (const float*)d_in[9];
    const float* ah_b      = (const float*)d_in[10];
    const float* ao_W      = (const float*)d_in[11];
    const float* ao_b      = (const float*)d_in[12];
    const float* gru_Wih   = (const float*)d_in[13];
    const float* gru_Whh   = (const float*)d_in[14];
    const float* gru_bih   = (const float*)d_in[15];
    const float* gru_bhh   = (const float*)d_in[16];
    const float* out_W     = (const float*)d_in[17];
    const float* out_b     = (const float*)d_in[18];

    float* out = (float*)d_out;
    float* logp = out;
    float* h1   = out + (size_t)BATCH * VDIM;
    float* nh   = h1 + (size_t)BATCH * HDIM;

    float *xe, *attn, *tmp, *fa, *gh, *hplus, *part;
    cudaGetSymbolAddress((void**)&xe, g_xe);
    cudaGetSymbolAddress((void**)&attn, g_attn);
    cudaGetSymbolAddress((void**)&tmp, g_tmp);
    cudaGetSymbolAddress((void**)&fa, g_fa);
    cudaGetSymbolAddress((void**)&gh, g_gh);
    cudaGetSymbolAddress((void**)&hplus, g_hplus);
    cudaGetSymbolAddress((void**)&part, g_part);

    const int SM_G32 = (3 * 64 * 36 + 3 * 32 * 36) * 4;
    const int SM_G64 = (3 * 64 * 36 + 3 * 64 * 36) * 4;
    const int SM_CH  = (3 * 64 * 36 + 3 * 24 * 36 + 3 * 64 * 36) * 4 + 64 * 26 * 4;
    cudaFuncSetAttribute(gemm_pipe<64>, cudaFuncAttributeMaxDynamicSharedMemorySize, SM_G64);
    cudaFuncSetAttribute(gru_chain, cudaFuncAttributeMaxDynamicSharedMemorySize, SM_CH);

    init_bar_kernel<<<1, 32>>>();
    embed_relu_kernel<<<BATCH, 256>>>(emb, x, xe);

    // attention MLP chain (split-K 8)
    gemm_pipe<32><<<dim3(HDIM / 32, 1, 8), 256, SM_G32>>>(feature, map_W, map_b,
                                                          part, FDIM, HDIM, FDIM / 8, 0);
    reduce_kernel<<<BH / 256, 256>>>(part, map_b, attention, fa, 8);  // fa = relu(.)+attention
    gemm_pipe<32><<<dim3(HDIM / 32, 1, 8), 256, SM_G32>>>(fa, ai_W, ai_b,
                                                          part, HDIM, HDIM, HDIM / 8, 0);
    reduce_kernel<<<BH / 256, 256>>>(part, ai_b, nullptr, attn, 8);
    gemm_pipe<32><<<dim3(HDIM / 32, 1, 8), 256, SM_G32>>>(attn, ah_W, ah_b,
                                                          part, HDIM, HDIM, HDIM / 8, 0);
    reduce_kernel<<<BH / 256, 256>>>(part, ah_b, nullptr, tmp, 8);
    gemm_pipe<32><<<dim3(HDIM / 32, 1, 8), 256, SM_G32>>>(tmp, ao_W, ao_b,
                                                          part, HDIM, HDIM, HDIM / 8, 0);
    reduce_kernel<<<BH / 256, 256>>>(part, ao_b, nullptr, attn, 8);

    // hplus = hiddens + attn (all layers)
    hplus_kernel<<<NLAYER * BH / 256, 256>>>(hiddens, attn, hplus);

    // all 8 gh GEMMs, one batched launch
    gemm_pipe<32><<<dim3(3 * HDIM / 32, NLAYER, 1), 256, SM_G32>>>(
        hplus, gru_Whh, gru_bhh, gh, HDIM, 3 * HDIM, HDIM, BH);

    // fused persistent GRU chain (all 8 layers, 1 launch)
    gru_chain<<<HDIM / 8, 384, SM_CH>>>(xe, nh, h1, gru_Wih, gru_bih, gh, hplus);

    // output projection + log-softmax
    gemm_pipe<64><<<dim3(VDIM / 64, 1, 1), 256, SM_G64>>>(
        nh + 7 * (size_t)BH, out_W, out_b, logp, HDIM, VDIM, HDIM, 0);
    log_softmax_kernel<<<BATCH, 1024>>>(logp);
}